// round 1
// baseline (speedup 1.0000x reference)
#include <cuda_runtime.h>
#include <cuda_bf16.h>
#include <math.h>

// ---------------- problem constants ----------------
#define BATCH   4
#define NSEQ    512
#define NDIM    1024
#define EDIM    64
#define HEADS   16
#define DOTD    64
#define FFN_H   2048
#define FFN_E   128
#define BN      (BATCH*NSEQ)          // 2048 token rows
#define NN      (NSEQ*NSEQ)           // 262144 per batch
#define BHN     (BATCH*HEADS)         // 64
#define EROWS   ((size_t)BATCH*NSEQ*NSEQ) // 1048576 edge rows
#define H_OUT_ELEMS (BN*NDIM)         // 2097152

// ---------------- scratch (device globals; no allocs allowed) ----------------
__device__ float g_hln [BN*NDIM];
__device__ float g_qkv [BN*3*NDIM];
__device__ float g_E   [(size_t)BHN*NN];   // (b*16+h, l*512+m)
__device__ float g_gate[(size_t)BHN*NN];
__device__ float g_H   [(size_t)BHN*NN];   // H_hat = clip(A)+E
__device__ float g_At  [(size_t)BHN*NN];   // softmax*gates
__device__ float g_vatt[BN*NDIM];
__device__ float g_h1  [BN*NDIM];          // h after O_h + residual
__device__ float g_h2  [BN*NDIM];          // LN of g_h1
__device__ float g_act [BN*FFN_H];

// ---------------- LayerNorm over 1024 ----------------
__global__ void __launch_bounds__(256) ln1024_kernel(
    const float* __restrict__ x, const float* __restrict__ g,
    const float* __restrict__ b, float* __restrict__ y)
{
    int row = blockIdx.x, t = threadIdx.x;
    const float* xr = x + (size_t)row * NDIM;
    float v[4]; float s = 0.f;
#pragma unroll
    for (int i = 0; i < 4; i++) { v[i] = xr[t + i*256]; s += v[i]; }
    __shared__ float red[8];
    int lane = t & 31, w = t >> 5;
#pragma unroll
    for (int o = 16; o; o >>= 1) s += __shfl_xor_sync(0xffffffff, s, o);
    if (lane == 0) red[w] = s;
    __syncthreads();
    float tot = 0.f;
#pragma unroll
    for (int i = 0; i < 8; i++) tot += red[i];
    float mu = tot * (1.0f/NDIM);
    __syncthreads();
    float q = 0.f;
#pragma unroll
    for (int i = 0; i < 4; i++) { float d = v[i]-mu; q += d*d; }
#pragma unroll
    for (int o = 16; o; o >>= 1) q += __shfl_xor_sync(0xffffffff, q, o);
    if (lane == 0) red[w] = q;
    __syncthreads();
    float qt = 0.f;
#pragma unroll
    for (int i = 0; i < 8; i++) qt += red[i];
    float rs = rsqrtf(qt * (1.0f/NDIM) + 1e-5f);
    float* yr = y + (size_t)row * NDIM;
#pragma unroll
    for (int i = 0; i < 4; i++) {
        int c = t + i*256;
        yr[c] = (v[i]-mu)*rs*g[c] + b[c];
    }
}

// ---------------- generic fp32 GEMM: C = act(A@W + bias) (+res) ----------------
// 128x128 tile, BK=8, 256 threads, 8x8 per thread.
__global__ void __launch_bounds__(256) gemm_kernel(
    const float* __restrict__ A, const float* __restrict__ W,
    const float* __restrict__ bias, const float* __restrict__ res,
    float* __restrict__ C, int M, int N, int K, int act)
{
    __shared__ float As[8*128];
    __shared__ float Bs[8*128];
    int t = threadIdx.x;
    int n0 = blockIdx.x * 128, m0 = blockIdx.y * 128;
    int tx = t & 15, ty = t >> 4;
    float acc[8][8];
#pragma unroll
    for (int i = 0; i < 8; i++)
#pragma unroll
        for (int j = 0; j < 8; j++) acc[i][j] = 0.f;

    int arow = t >> 1;            // 0..127
    int acol = (t & 1) * 4;       // 0 or 4
    int brow = t >> 5;            // 0..7
    int bcol = (t & 31) * 4;
    const float* Aptr = A + (size_t)(m0 + arow)*K + acol;
    const float* Wbase = W + (size_t)brow*N + n0 + bcol;

    for (int k0 = 0; k0 < K; k0 += 8) {
        float4 av = *(const float4*)(Aptr + k0);
        As[(acol+0)*128 + arow] = av.x;
        As[(acol+1)*128 + arow] = av.y;
        As[(acol+2)*128 + arow] = av.z;
        As[(acol+3)*128 + arow] = av.w;
        float4 bv = *(const float4*)(Wbase + (size_t)k0*N);
        *(float4*)&Bs[brow*128 + bcol] = bv;
        __syncthreads();
#pragma unroll
        for (int k = 0; k < 8; k++) {
            float a[8], bb[8];
            *(float4*)&a[0]  = *(float4*)&As[k*128 + ty*8];
            *(float4*)&a[4]  = *(float4*)&As[k*128 + ty*8 + 4];
            *(float4*)&bb[0] = *(float4*)&Bs[k*128 + tx*8];
            *(float4*)&bb[4] = *(float4*)&Bs[k*128 + tx*8 + 4];
#pragma unroll
            for (int i = 0; i < 8; i++)
#pragma unroll
                for (int j = 0; j < 8; j++)
                    acc[i][j] += a[i]*bb[j];
        }
        __syncthreads();
    }
#pragma unroll
    for (int i = 0; i < 8; i++) {
        int m = m0 + ty*8 + i;
#pragma unroll
        for (int j = 0; j < 8; j += 4) {
            int n = n0 + tx*8 + j;
            float4 v;
            v.x = acc[i][j+0]; v.y = acc[i][j+1]; v.z = acc[i][j+2]; v.w = acc[i][j+3];
            float4 bi = *(const float4*)&bias[n];
            v.x += bi.x; v.y += bi.y; v.z += bi.z; v.w += bi.w;
            if (act) {
                v.x = v.x > 0.f ? v.x : expm1f(v.x);
                v.y = v.y > 0.f ? v.y : expm1f(v.y);
                v.z = v.z > 0.f ? v.z : expm1f(v.z);
                v.w = v.w > 0.f ? v.w : expm1f(v.w);
            }
            if (res) {
                float4 r = *(const float4*)&res[(size_t)m*N + n];
                v.x += r.x; v.y += r.y; v.z += r.z; v.w += r.w;
            }
            *(float4*)&C[(size_t)m*N + n] = v;
        }
    }
}

// ---------------- e -> LN -> E proj, sigmoid(G proj) ----------------
// Block handles 64 consecutive edge rows (same (b,l), contiguous m).
__global__ void __launch_bounds__(256) eg_kernel(
    const float* __restrict__ e,
    const float* __restrict__ lng, const float* __restrict__ lnb,
    const float* __restrict__ WE, const float* __restrict__ bE,
    const float* __restrict__ WG, const float* __restrict__ bG)
{
    __shared__ float xs[64*65];
    __shared__ float wE[64*16], wG[64*16];
    __shared__ float ob[32*65];
    __shared__ float sg[64], sb[64], sbE[16], sbG[16];
    int t = threadIdx.x;
    size_t row0 = (size_t)blockIdx.x * 64;

    for (int i = t; i < 1024; i += 256) { wE[i] = WE[i]; wG[i] = WG[i]; }
    if (t < 64) { sg[t] = lng[t]; sb[t] = lnb[t]; }
    if (t < 16) { sbE[t] = bE[t]; sbG[t] = bG[t]; }
#pragma unroll
    for (int i = 0; i < 16; i++) {
        int idx = t + i*256;
        int r = idx >> 6, c = idx & 63;
        xs[r*65 + c] = e[row0*64 + idx];
    }
    __syncthreads();
    // LN per row (quad of threads per row)
    {
        int r = t >> 2, part = t & 3;
        float lv[16]; float s = 0.f;
#pragma unroll
        for (int k = 0; k < 16; k++) { lv[k] = xs[r*65 + part*16 + k]; s += lv[k]; }
        s += __shfl_xor_sync(0xffffffff, s, 1);
        s += __shfl_xor_sync(0xffffffff, s, 2);
        float mu = s * (1.0f/64.0f);
        float q = 0.f;
#pragma unroll
        for (int k = 0; k < 16; k++) { float d = lv[k]-mu; q += d*d; }
        q += __shfl_xor_sync(0xffffffff, q, 1);
        q += __shfl_xor_sync(0xffffffff, q, 2);
        float rsg = rsqrtf(q * (1.0f/64.0f) + 1e-5f);
#pragma unroll
        for (int k = 0; k < 16; k++) {
            int c = part*16 + k;
            xs[r*65 + c] = (lv[k]-mu)*rsg*sg[c] + sb[c];
        }
    }
    __syncthreads();
    // 32 outputs (16 E, 16 G) x 64 rows
    {
        int o = t & 31, rg = t >> 5;
        bool isE = (o < 16);
        int oo = isE ? o : o - 16;
        const float* wp = isE ? wE : wG;
#pragma unroll
        for (int i = 0; i < 8; i++) {
            int rr = rg*8 + i;
            float a = 0.f;
#pragma unroll
            for (int k = 0; k < 64; k++) a += xs[rr*65 + k] * wp[k*16 + oo];
            a += isE ? sbE[oo] : sbG[oo];
            if (!isE) a = 1.0f / (1.0f + expf(-a));
            ob[o*65 + rr] = a;
        }
    }
    __syncthreads();
    int b_ = (int)(row0 >> 18);
    int rem = (int)(row0 & (NN - 1));
    int l = rem >> 9, m0 = rem & 511;
#pragma unroll
    for (int i = 0; i < 8; i++) {
        int idx = t + i*256;
        int o = idx >> 6, rr = idx & 63;
        float val = ob[o*65 + rr];
        int hd = o & 15;
        size_t dst = ((size_t)(b_*HEADS + hd))*NN + (size_t)l*512 + m0 + rr;
        if (o < 16) g_E[dst] = val; else g_gate[dst] = val;
    }
}

// ---------------- Q@K^T, scale, clip, +E -> H_hat ----------------
__global__ void __launch_bounds__(256) qk_kernel(const float* __restrict__ qkv)
{
    __shared__ float Qs[64*65];  // [d][l]
    __shared__ float Ks[64*65];  // [d][m]
    int t = threadIdx.x;
    int m0 = blockIdx.x * 64, l0 = blockIdx.y * 64;
    int z = blockIdx.z;
    int b = z >> 4, hd = z & 15;
    const float* qb = qkv + (size_t)b*NSEQ*3*NDIM + hd;
#pragma unroll
    for (int i = 0; i < 16; i++) {
        int idx = t + i*256;
        int d = idx & 63, r = idx >> 6;
        Qs[d*65 + r] = qb[(size_t)(l0 + r)*(3*NDIM) + d*16];
        Ks[d*65 + r] = qb[(size_t)(m0 + r)*(3*NDIM) + NDIM + d*16];
    }
    __syncthreads();
    int tx = t & 15, ty = t >> 4;
    float acc[4][4];
#pragma unroll
    for (int i = 0; i < 4; i++)
#pragma unroll
        for (int j = 0; j < 4; j++) acc[i][j] = 0.f;
#pragma unroll 4
    for (int d = 0; d < 64; d++) {
        float a[4], bb[4];
#pragma unroll
        for (int i = 0; i < 4; i++) a[i]  = Qs[d*65 + ty*4 + i];
#pragma unroll
        for (int j = 0; j < 4; j++) bb[j] = Ks[d*65 + tx*4 + j];
#pragma unroll
        for (int i = 0; i < 4; i++)
#pragma unroll
            for (int j = 0; j < 4; j++) acc[i][j] += a[i]*bb[j];
    }
    size_t base = (size_t)z * NN;
#pragma unroll
    for (int i = 0; i < 4; i++) {
        int l = l0 + ty*4 + i;
        size_t ro = base + (size_t)l*512 + m0 + tx*4;
        float4 ev = *(const float4*)&g_E[ro];
        float4 hv;
        hv.x = fminf(fmaxf(acc[i][0]*0.125f, -5.f), 5.f) + ev.x;
        hv.y = fminf(fmaxf(acc[i][1]*0.125f, -5.f), 5.f) + ev.y;
        hv.z = fminf(fmaxf(acc[i][2]*0.125f, -5.f), 5.f) + ev.z;
        hv.w = fminf(fmaxf(acc[i][3]*0.125f, -5.f), 5.f) + ev.w;
        *(float4*)&g_H[ro] = hv;
    }
}

// ---------------- softmax over m, * gates ----------------
__global__ void __launch_bounds__(256) softmax_kernel()
{
    int row = blockIdx.x;               // z*512 + l
    int t = threadIdx.x;
    size_t base = (size_t)row * 512;
    float v0 = g_H[base + t], v1 = g_H[base + 256 + t];
    __shared__ float red[8];
    int lane = t & 31, w = t >> 5;
    float mx = fmaxf(v0, v1);
#pragma unroll
    for (int o = 16; o; o >>= 1) mx = fmaxf(mx, __shfl_xor_sync(0xffffffff, mx, o));
    if (lane == 0) red[w] = mx;
    __syncthreads();
    float m = red[0];
#pragma unroll
    for (int i = 1; i < 8; i++) m = fmaxf(m, red[i]);
    __syncthreads();
    float e0 = expf(v0 - m), e1 = expf(v1 - m);
    float s = e0 + e1;
#pragma unroll
    for (int o = 16; o; o >>= 1) s += __shfl_xor_sync(0xffffffff, s, o);
    if (lane == 0) red[w] = s;
    __syncthreads();
    float tot = 0.f;
#pragma unroll
    for (int i = 0; i < 8; i++) tot += red[i];
    float inv = 1.0f / tot;
    g_At[base + t]       = e0 * inv * g_gate[base + t];
    g_At[base + 256 + t] = e1 * inv * g_gate[base + 256 + t];
}

// ---------------- A_tild @ V -> V_att (written in (b,l,k*16+h) layout) ----------------
__global__ void __launch_bounds__(256) av_kernel(const float* __restrict__ qkv)
{
    __shared__ float As[64*65]; // [m][l]
    __shared__ float Vs[64*64]; // [m][k]
    int t = threadIdx.x;
    int l0 = blockIdx.x * 64;
    int z = blockIdx.y;
    int b = z >> 4, hd = z & 15;
    int tx = t & 15, ty = t >> 4;
    const float* vb = qkv + (size_t)b*NSEQ*3*NDIM + 2*NDIM + hd;
    size_t abase = (size_t)z*NN + (size_t)l0*512;
    float acc[4][4];
#pragma unroll
    for (int i = 0; i < 4; i++)
#pragma unroll
        for (int j = 0; j < 4; j++) acc[i][j] = 0.f;

    for (int mt = 0; mt < 512; mt += 64) {
#pragma unroll
        for (int i = 0; i < 16; i++) {
            int idx = t + i*256;
            int c = idx & 63, r = idx >> 6;
            As[c*65 + r] = g_At[abase + (size_t)r*512 + mt + c];
            Vs[r*64 + c] = vb[(size_t)(mt + r)*(3*NDIM) + c*16];
        }
        __syncthreads();
#pragma unroll 4
        for (int m = 0; m < 64; m++) {
            float a[4], vv[4];
#pragma unroll
            for (int i = 0; i < 4; i++) a[i]  = As[m*65 + ty*4 + i];
#pragma unroll
            for (int j = 0; j < 4; j++) vv[j] = Vs[m*64 + tx*4 + j];
#pragma unroll
            for (int i = 0; i < 4; i++)
#pragma unroll
                for (int j = 0; j < 4; j++) acc[i][j] += a[i]*vv[j];
        }
        __syncthreads();
    }
#pragma unroll
    for (int i = 0; i < 4; i++) {
        int l = l0 + ty*4 + i;
#pragma unroll
        for (int j = 0; j < 4; j++) {
            int k = tx*4 + j;
            g_vatt[(size_t)(b*NSEQ + l)*NDIM + k*16 + hd] = acc[i][j];
        }
    }
}

// ---------------- fused e-out: H_hat@W_Oe + b + e -> LN -> FFN(64->128->64) -> +res ----------------
#define EOUT_SMEM_FLOATS 31360
__global__ void __launch_bounds__(256) eout_kernel(
    const float* __restrict__ e,
    const float* __restrict__ WOe, const float* __restrict__ bOe,
    const float* __restrict__ lng, const float* __restrict__ lnb,
    const float* __restrict__ W1, const float* __restrict__ b1,
    const float* __restrict__ W2, const float* __restrict__ b2,
    float* __restrict__ eout)
{
    extern __shared__ float sm[];
    float* W1s  = sm;              // 8192
    float* W2s  = W1s  + 8192;     // 8192
    float* WOes = W2s  + 8192;     // 1024
    float* xs   = WOes + 1024;     // 64*65 = 4160
    float* hs   = xs   + 4160;     // 64*129 = 8256
    float* Hsm  = hs   + 8256;     // 16*64 = 1024
    float* smu  = Hsm  + 1024;     // 64
    float* srs  = smu  + 64;       // 64
    float* sbOe = srs  + 64;       // 64
    float* sge  = sbOe + 64;       // 64
    float* sbe  = sge  + 64;       // 64
    float* sb1  = sbe  + 64;       // 128
    float* sb2  = sb1  + 128;      // 64  -> total 31360

    int t = threadIdx.x;
    size_t row0 = (size_t)blockIdx.x * 64;
    int b_ = (int)(row0 >> 18);
    int rem = (int)(row0 & (NN - 1));
    int l = rem >> 9, m0 = rem & 511;

    for (int i = t; i < 8192; i += 256) { W1s[i] = W1[i]; W2s[i] = W2[i]; }
    for (int i = t; i < 1024; i += 256) WOes[i] = WOe[i];
    if (t < 64) { sbOe[t] = bOe[t]; sge[t] = lng[t]; sbe[t] = lnb[t]; sb2[t] = b2[t]; }
    if (t < 128) sb1[t] = b1[t];
    for (int i = t; i < 1024; i += 256) {
        int hd = i >> 6, r = i & 63;
        Hsm[hd*64 + r] = g_H[((size_t)(b_*HEADS + hd))*NN + (size_t)l*512 + m0 + r];
    }
    __syncthreads();

    int tx = t & 15, ty = t >> 4;
    // Phase A: xs = H@WOe + bOe + e  (64 x 64)
    {
        float acc[4][4];
#pragma unroll
        for (int i = 0; i < 4; i++)
#pragma unroll
            for (int j = 0; j < 4; j++) acc[i][j] = 0.f;
#pragma unroll
        for (int hd = 0; hd < 16; hd++) {
            float a[4], w[4];
#pragma unroll
            for (int i = 0; i < 4; i++) a[i] = Hsm[hd*64 + ty*4 + i];
#pragma unroll
            for (int j = 0; j < 4; j++) w[j] = WOes[hd*64 + tx*4 + j];
#pragma unroll
            for (int i = 0; i < 4; i++)
#pragma unroll
                for (int j = 0; j < 4; j++) acc[i][j] += a[i]*w[j];
        }
#pragma unroll
        for (int i = 0; i < 4; i++) {
            int r = ty*4 + i;
            float4 ev = *(const float4*)&e[(row0 + r)*64 + tx*4];
            xs[r*65 + tx*4 + 0] = acc[i][0] + sbOe[tx*4+0] + ev.x;
            xs[r*65 + tx*4 + 1] = acc[i][1] + sbOe[tx*4+1] + ev.y;
            xs[r*65 + tx*4 + 2] = acc[i][2] + sbOe[tx*4+2] + ev.z;
            xs[r*65 + tx*4 + 3] = acc[i][3] + sbOe[tx*4+3] + ev.w;
        }
    }
    __syncthreads();
    // Phase B: LN stats per row
    {
        int r = t >> 2, part = t & 3;
        float lv[16]; float s = 0.f;
#pragma unroll
        for (int k = 0; k < 16; k++) { lv[k] = xs[r*65 + part*16 + k]; s += lv[k]; }
        s += __shfl_xor_sync(0xffffffff, s, 1);
        s += __shfl_xor_sync(0xffffffff, s, 2);
        float mu = s * (1.0f/64.0f);
        float q = 0.f;
#pragma unroll
        for (int k = 0; k < 16; k++) { float d = lv[k]-mu; q += d*d; }
        q += __shfl_xor_sync(0xffffffff, q, 1);
        q += __shfl_xor_sync(0xffffffff, q, 2);
        if (part == 0) { smu[r] = mu; srs[r] = rsqrtf(q*(1.0f/64.0f) + 1e-5f); }
    }
    __syncthreads();
    // Phase C: hidden = elu( LN(xs) @ W1 + b1 )  (64 x 128)
    {
        float acc[4][8];
#pragma unroll
        for (int i = 0; i < 4; i++)
#pragma unroll
            for (int j = 0; j < 8; j++) acc[i][j] = 0.f;
        float mur[4], rsr[4];
#pragma unroll
        for (int i = 0; i < 4; i++) { mur[i] = smu[ty*4+i]; rsr[i] = srs[ty*4+i]; }
#pragma unroll 4
        for (int k = 0; k < 64; k++) {
            float gk = sge[k], bk = sbe[k];
            float xn[4];
#pragma unroll
            for (int i = 0; i < 4; i++)
                xn[i] = (xs[(ty*4+i)*65 + k] - mur[i]) * rsr[i] * gk + bk;
            float w[8];
            *(float4*)&w[0] = *(float4*)&W1s[k*128 + tx*8];
            *(float4*)&w[4] = *(float4*)&W1s[k*128 + tx*8 + 4];
#pragma unroll
            for (int i = 0; i < 4; i++)
#pragma unroll
                for (int j = 0; j < 8; j++) acc[i][j] += xn[i]*w[j];
        }
#pragma unroll
        for (int i = 0; i < 4; i++)
#pragma unroll
            for (int j = 0; j < 8; j++) {
                float v = acc[i][j] + sb1[tx*8 + j];
                v = v > 0.f ? v : expm1f(v);
                hs[(ty*4+i)*129 + tx*8 + j] = v;
            }
    }
    __syncthreads();
    // Phase E: out = hs @ W2 + b2 + xs(residual)
    {
        float acc[4][4];
#pragma unroll
        for (int i = 0; i < 4; i++)
#pragma unroll
            for (int j = 0; j < 4; j++) acc[i][j] = 0.f;
#pragma unroll 4
        for (int j2 = 0; j2 < 128; j2++) {
            float hv[4], w[4];
#pragma unroll
            for (int i = 0; i < 4; i++) hv[i] = hs[(ty*4+i)*129 + j2];
            *(float4*)&w[0] = *(float4*)&W2s[j2*64 + tx*4];
#pragma unroll
            for (int i = 0; i < 4; i++)
#pragma unroll
                for (int j = 0; j < 4; j++) acc[i][j] += hv[i]*w[j];
        }
#pragma unroll
        for (int i = 0; i < 4; i++) {
            int r = ty*4 + i;
            int c = tx*4;
            float4 ov;
            ov.x = acc[i][0] + sb2[c+0] + xs[r*65 + c+0];
            ov.y = acc[i][1] + sb2[c+1] + xs[r*65 + c+1];
            ov.z = acc[i][2] + sb2[c+2] + xs[r*65 + c+2];
            ov.w = acc[i][3] + sb2[c+3] + xs[r*65 + c+3];
            *(float4*)&eout[(row0 + r)*64 + c] = ov;
        }
    }
}

// ---------------- host launcher ----------------
extern "C" void kernel_launch(void* const* d_in, const int* in_sizes, int n_in,
                              void* d_out, int out_size)
{
    const float* h        = (const float*)d_in[0];
    const float* e        = (const float*)d_in[1];
    const float* ln_h_g   = (const float*)d_in[2];
    const float* ln_h_b   = (const float*)d_in[3];
    const float* ln_e_g   = (const float*)d_in[4];
    const float* ln_e_b   = (const float*)d_in[5];
    const float* W_E      = (const float*)d_in[6];
    const float* b_E      = (const float*)d_in[7];
    const float* W_QKV    = (const float*)d_in[8];
    const float* b_QKV    = (const float*)d_in[9];
    const float* W_G      = (const float*)d_in[10];
    const float* b_G      = (const float*)d_in[11];
    const float* W_Oh     = (const float*)d_in[12];
    const float* b_Oh     = (const float*)d_in[13];
    const float* ffn_ln_h_g = (const float*)d_in[14];
    const float* ffn_ln_h_b = (const float*)d_in[15];
    const float* W_h1     = (const float*)d_in[16];
    const float* b_h1     = (const float*)d_in[17];
    const float* W_h2     = (const float*)d_in[18];
    const float* b_h2     = (const float*)d_in[19];
    const float* W_Oe     = (const float*)d_in[20];
    const float* b_Oe     = (const float*)d_in[21];
    const float* ffn_ln_e_g = (const float*)d_in[22];
    const float* ffn_ln_e_b = (const float*)d_in[23];
    const float* W_e1     = (const float*)d_in[24];
    const float* b_e1     = (const float*)d_in[25];
    const float* W_e2     = (const float*)d_in[26];
    const float* b_e2     = (const float*)d_in[27];

    float* out_h = (float*)d_out;
    float* out_e = out_h + H_OUT_ELEMS;

    float *p_hln, *p_qkv, *p_vatt, *p_h1, *p_h2, *p_act;
    cudaGetSymbolAddress((void**)&p_hln,  g_hln);
    cudaGetSymbolAddress((void**)&p_qkv,  g_qkv);
    cudaGetSymbolAddress((void**)&p_vatt, g_vatt);
    cudaGetSymbolAddress((void**)&p_h1,   g_h1);
    cudaGetSymbolAddress((void**)&p_h2,   g_h2);
    cudaGetSymbolAddress((void**)&p_act,  g_act);

    // h path pre-attention
    ln1024_kernel<<<BN, 256>>>(h, ln_h_g, ln_h_b, p_hln);
    gemm_kernel<<<dim3(3*NDIM/128, BN/128), 256>>>(p_hln, W_QKV, b_QKV, nullptr, p_qkv,
                                                   BN, 3*NDIM, NDIM, 0);
    // e path: LN + E/G projections
    eg_kernel<<<(unsigned)(EROWS/64), 256>>>(e, ln_e_g, ln_e_b, W_E, b_E, W_G, b_G);
    // attention
    qk_kernel<<<dim3(8, 8, BHN), 256>>>(p_qkv);
    softmax_kernel<<<BHN*NSEQ, 256>>>();
    av_kernel<<<dim3(8, BHN), 256>>>(p_qkv);
    // h path post-attention
    gemm_kernel<<<dim3(NDIM/128, BN/128), 256>>>(p_vatt, W_Oh, b_Oh, h, p_h1,
                                                 BN, NDIM, NDIM, 0);
    ln1024_kernel<<<BN, 256>>>(p_h1, ffn_ln_h_g, ffn_ln_h_b, p_h2);
    gemm_kernel<<<dim3(FFN_H/128, BN/128), 256>>>(p_h2, W_h1, b_h1, nullptr, p_act,
                                                  BN, FFN_H, NDIM, 1);
    gemm_kernel<<<dim3(NDIM/128, BN/128), 256>>>(p_act, W_h2, b_h2, p_h1, out_h,
                                                 BN, NDIM, FFN_H, 0);
    // fused e output path
    cudaFuncSetAttribute(eout_kernel, cudaFuncAttributeMaxDynamicSharedMemorySize,
                         EOUT_SMEM_FLOATS * 4);
    eout_kernel<<<(unsigned)(EROWS/64), 256, EOUT_SMEM_FLOATS * 4>>>(
        e, W_Oe, b_Oe, ffn_ln_e_g, ffn_ln_e_b, W_e1, b_e1, W_e2, b_e2, out_e);
}